// round 6
// baseline (speedup 1.0000x reference)
#include <cuda_runtime.h>
#include <cuda_bf16.h>
#include <cstdint>

// out = sum_i | cumsum(x0 - x1)_i |, x = d_in[0] as (2, N) fp32, N = 2^23.
// Single persistent kernel, 148 blocks (1/SM), 1024 threads, 224 KB dynamic smem.
//   Phase A (full blocks): cp.async.cg stages the x0 chunk into smem (register-free
//     MLP, 224 KB/SM in flight); x1 via double-buffered LDG.128; diff written back
//     in place; block sum.
//   Grid sync (self-resetting double-counter, graph-replay safe).
//   Phase B: block/warp prefix + per-tile warp shuffle scans from smem, sum|cdf|.
//   Grid sync 2, block 0 reduces partials (fp64) -> fp32 scalar.

#define GRID_N   148
#define TPB      1024
#define NWARP    32
#define BLK_F4   14336            // float4 per block (57344 elems, 224 KB smem)
#define WARP_F4  448              // float4 per warp
#define LANE_J   14               // tiles per warp (float4 per lane per tile)

__device__ float    g_blockSums[GRID_N];
__device__ float    g_blockPartials[GRID_N];
__device__ unsigned g_ctrA;       // zero-initialized at module load
__device__ unsigned g_ctrB;

__device__ __forceinline__ void grid_sync(unsigned* ctr, unsigned* other) {
    __syncthreads();
    if (threadIdx.x == 0) {
        __threadfence();
        unsigned v = atomicAdd(ctr, 1u);
        if (v == GRID_N - 1) {
            *other = 0u;
            __threadfence();
            atomicAdd(ctr, 1u);               // release: ctr -> GRID_N + 1
        }
        while (*(volatile unsigned*)ctr < GRID_N + 1u) { }
        __threadfence();
    }
    __syncthreads();
}

__global__ void __launch_bounds__(TPB) emd_fused(const float* __restrict__ x,
                                                 float* __restrict__ out, int N) {
    extern __shared__ float4 sdiff[];         // BLK_F4 float4
    __shared__ float sWarpSums[NWARP];
    __shared__ float sWarpAcc[NWARP];
    __shared__ float sBlockPrefix;

    const int  tid  = threadIdx.x;
    const int  w    = tid >> 5;
    const int  lane = tid & 31;
    const int  bid  = blockIdx.x;
    const long tot4 = (long)N / 4;            // 2^21 float4 (multiple of 32)

    const float4* x0 = (const float4*)x;
    const float4* x1 = (const float4*)(x + N);

    const long blockStart4 = (long)bid * BLK_F4;
    const int  warpLocal4  = w * WARP_F4;
    const bool fullBlock   = (blockStart4 + BLK_F4) <= tot4;

    // ---------------- Phase A ----------------
    float s = 0.f;
    if (fullBlock) {
        // 1) register-free x0 stream: 14 cp.async.cg per thread -> sdiff
        unsigned int sm_base =
            (unsigned int)__cvta_generic_to_shared(&sdiff[warpLocal4 + lane]);
        const float4* p0 = x0 + blockStart4 + warpLocal4 + lane;
#pragma unroll
        for (int j = 0; j < LANE_J; ++j) {
            asm volatile("cp.async.cg.shared.global [%0], [%1], 16;\n"
                         :: "r"(sm_base + j * 32 * 16), "l"(p0 + j * 32)
                         : "memory");
        }
        asm volatile("cp.async.commit_group;\n" ::: "memory");

        // 2) x1 stream via LDG.128, double-buffered groups of 4 tiles
        const float4* p1 = x1 + blockStart4 + warpLocal4 + lane;
        float4 b[4], bn[4];
#pragma unroll
        for (int u = 0; u < 4; ++u) b[u] = p1[u * 32];

        asm volatile("cp.async.wait_group 0;\n" ::: "memory");
        // Each thread reads exactly the smem slots its own cp.async wrote,
        // so per-thread wait is sufficient ordering.

        const int gsz[4] = {4, 4, 4, 2};      // tile groups: 4+4+4+2 = 14
        const int nsz[4] = {4, 4, 2, 0};
#pragma unroll
        for (int g = 0; g < 4; ++g) {
#pragma unroll
            for (int u = 0; u < 4; ++u)       // prefetch next group
                if (u < nsz[g]) bn[u] = p1[((g + 1) * 4 + u) * 32];
#pragma unroll
            for (int u = 0; u < 4; ++u) {
                if (u < gsz[g]) {
                    int idx = warpLocal4 + (g * 4 + u) * 32 + lane;
                    float4 a = sdiff[idx];    // staged x0
                    float4 d;
                    d.x = a.x - b[u].x; d.y = a.y - b[u].y;
                    d.z = a.z - b[u].z; d.w = a.w - b[u].w;
                    sdiff[idx] = d;
                    s += (d.x + d.y) + (d.z + d.w);
                }
            }
#pragma unroll
            for (int u = 0; u < 4; ++u) b[u] = bn[u];
        }
    } else {
        // ragged tail blocks (bid >= 146): guarded LDG path
#pragma unroll
        for (int j = 0; j < LANE_J; ++j) {
            long base = blockStart4 + warpLocal4 + j * 32;   // multiple of 32
            if (base < tot4) {
                long t4 = base + lane;
                float4 a = x0[t4];
                float4 b = x1[t4];
                float4 d;
                d.x = a.x - b.x; d.y = a.y - b.y;
                d.z = a.z - b.z; d.w = a.w - b.w;
                sdiff[warpLocal4 + j * 32 + lane] = d;
                s += (d.x + d.y) + (d.z + d.w);
            }
        }
    }

#pragma unroll
    for (int off = 16; off; off >>= 1)
        s += __shfl_down_sync(0xffffffffu, s, off);
    if (lane == 0) sWarpSums[w] = s;
    __syncthreads();
    if (tid == 0) {
        float bs = 0.f;
#pragma unroll
        for (int i = 0; i < NWARP; ++i) bs += sWarpSums[i];
        g_blockSums[bid] = bs;
    }

    grid_sync(&g_ctrA, &g_ctrB);

    // ---------------- Phase B: prefixes + tile scans from smem ----------------
    if (w == 0) {
        float p = 0.f;
#pragma unroll
        for (int i = lane; i < GRID_N; i += 32)
            if (i < bid) p += g_blockSums[i];
#pragma unroll
        for (int off = 16; off; off >>= 1)
            p += __shfl_down_sync(0xffffffffu, p, off);
        if (lane == 0) sBlockPrefix = p;
    }
    __syncthreads();

    float carry = sBlockPrefix;
    for (int i = 0; i < w; ++i) carry += sWarpSums[i];

    float acc = 0.f;
#pragma unroll
    for (int j = 0; j < LANE_J; ++j) {
        long base = blockStart4 + warpLocal4 + j * 32;
        if (base < tot4) {
            float4 d = sdiff[warpLocal4 + j * 32 + lane];  // conflict-free LDS.128
            float s0 = d.x;
            float s1 = s0 + d.y;
            float s2 = s1 + d.z;
            float s3 = s2 + d.w;

            float v = s3;                      // warp inclusive scan of lane totals
#pragma unroll
            for (int off = 1; off < 32; off <<= 1) {
                float n = __shfl_up_sync(0xffffffffu, v, off);
                if (lane >= off) v += n;
            }
            float base_p = carry + (v - s3);   // lane-exclusive prefix
            acc += fabsf(base_p + s0) + fabsf(base_p + s1)
                 + fabsf(base_p + s2) + fabsf(base_p + s3);
            carry += __shfl_sync(0xffffffffu, v, 31);
        }
    }

#pragma unroll
    for (int off = 16; off; off >>= 1)
        acc += __shfl_down_sync(0xffffffffu, acc, off);
    if (lane == 0) sWarpAcc[w] = acc;
    __syncthreads();
    if (tid == 0) {
        float bp = 0.f;
#pragma unroll
        for (int i = 0; i < NWARP; ++i) bp += sWarpAcc[i];
        g_blockPartials[bid] = bp;
    }

    grid_sync(&g_ctrB, &g_ctrA);

    // ---------------- Final: block 0 reduces 148 partials (fp64) ----------------
    if (bid == 0 && w == 0) {
        double p = 0.0;
#pragma unroll
        for (int i = lane; i < GRID_N; i += 32)
            p += (double)g_blockPartials[i];
#pragma unroll
        for (int off = 16; off; off >>= 1)
            p += __shfl_down_sync(0xffffffffu, p, off);
        if (lane == 0) out[0] = (float)p;
    }
}

extern "C" void kernel_launch(void* const* d_in, const int* in_sizes, int n_in,
                              void* d_out, int out_size) {
    const float* x = (const float*)d_in[0];
    int N = in_sizes[0] / 2;                  // 8388608
    size_t smem = (size_t)BLK_F4 * sizeof(float4);   // 229376 B

    static bool attr_done = false;
    if (!attr_done) {
        cudaFuncSetAttribute(emd_fused,
                             cudaFuncAttributeMaxDynamicSharedMemorySize,
                             (int)smem);
        attr_done = true;
    }
    emd_fused<<<GRID_N, TPB, smem>>>(x, (float*)d_out, N);
}